// round 6
// baseline (speedup 1.0000x reference)
#include <cuda_runtime.h>
#include <math_constants.h>
#include <cstdint>

// Problem constants
#define BATCH 128
#define TLEN  256
#define CDIM  768
#define MROWS (BATCH * TLEN)     // 32768
#define HALF  (CDIM / 2)         // 384

// ---------------------------------------------------------------------------
// Device-global scratch (tf32 bit arrays are k-permuted within 8-groups:
// pos(k) = ((k&3)<<1) | ((k>>2)&1), so mma pairs (lc, lc+4) are adjacent)
// ---------------------------------------------------------------------------
__device__ __align__(256) uint32_t g_xt[(size_t)MROWS * CDIM];          // x, tf32 perm
__device__ __align__(256) uint32_t g_wt[(size_t)3 * CDIM * CDIM];       // W^T [z][n][k], tf32 perm
__device__ __align__(256) uint32_t g_qt[(size_t)MROWS * CDIM];          // q (RoPE'd), tf32 perm
__device__ __align__(256) uint32_t g_kt[(size_t)MROWS * CDIM];          // k (RoPE'd), tf32 perm
__device__ __align__(256) float    g_v[(size_t)MROWS * CDIM];           // v, fp32
__device__ __align__(256) float    g_S[(size_t)BATCH * TLEN * TLEN];
__device__ __align__(256) float    g_cos[TLEN * HALF];
__device__ __align__(256) float    g_sin[TLEN * HALF];

// ---------------------------------------------------------------------------
// Helpers
// ---------------------------------------------------------------------------
__device__ __forceinline__ uint32_t f2tf(float f) {
    uint32_t r;
    asm("cvt.rna.tf32.f32 %0, %1;" : "=r"(r) : "f"(f));
    return r;
}
__device__ __forceinline__ uint32_t smem_u32(const void* p) {
    uint32_t a;
    asm("{ .reg .u64 t; cvta.to.shared.u64 t, %1; cvt.u32.u64 %0, t; }" : "=r"(a) : "l"(p));
    return a;
}
#define CP16(dst, src) asm volatile("cp.async.cg.shared.global [%0], [%1], 16;" :: "r"(dst), "l"(src))
#define CP_COMMIT()    asm volatile("cp.async.commit_group;" ::: "memory")
#define CP_WAIT1()     asm volatile("cp.async.wait_group 1;" ::: "memory")
#define CP_WAIT0()     asm volatile("cp.async.wait_group 0;" ::: "memory")

__device__ __forceinline__ void mma_tf32(float* d, const uint32_t* a, const uint32_t* b) {
    asm volatile(
        "mma.sync.aligned.m16n8k8.row.col.f32.tf32.tf32.f32 "
        "{%0,%1,%2,%3}, {%4,%5,%6,%7}, {%8,%9}, {%0,%1,%2,%3};"
        : "+f"(d[0]), "+f"(d[1]), "+f"(d[2]), "+f"(d[3])
        : "r"(a[0]), "r"(a[1]), "r"(a[2]), "r"(a[3]), "r"(b[0]), "r"(b[1]));
}

__device__ __forceinline__ int kperm(int k) {       // permute within 8-group
    return (k & ~7) | (((k & 3) << 1) | ((k >> 2) & 1));
}

// ---------------------------------------------------------------------------
// RoPE tables
// ---------------------------------------------------------------------------
__global__ void rope_table_kernel() {
    int idx = blockIdx.x * blockDim.x + threadIdx.x;
    if (idx >= TLEN * HALF) return;
    int t = idx / HALF;
    int j = idx % HALF;
    float theta = expf(-2.0f * (float)j * (1.0f / 768.0f) * 9.210340371976184f);
    float ang = (float)t * theta;
    float s, c;
    sincosf(ang, &s, &c);
    g_cos[idx] = c;
    g_sin[idx] = s;
}

// ---------------------------------------------------------------------------
// Convert x -> tf32 bits, k-permuted. One thread per 8 consecutive k.
// ---------------------------------------------------------------------------
__global__ void convert_x_kernel(const float* __restrict__ x) {
    size_t base = ((size_t)blockIdx.x * blockDim.x + threadIdx.x) * 8;
    float4 v0 = *(const float4*)(x + base);
    float4 v1 = *(const float4*)(x + base + 4);
    uint4 o0 = make_uint4(f2tf(v0.x), f2tf(v1.x), f2tf(v0.y), f2tf(v1.y));
    uint4 o1 = make_uint4(f2tf(v0.z), f2tf(v1.z), f2tf(v0.w), f2tf(v1.w));
    *(uint4*)(g_xt + base) = o0;
    *(uint4*)(g_xt + base + 4) = o1;
}

// ---------------------------------------------------------------------------
// Convert W -> W^T [n][k], tf32 bits, k-permuted.
// ---------------------------------------------------------------------------
__global__ void convert_w_kernel(const float* __restrict__ Wq,
                                 const float* __restrict__ Wk,
                                 const float* __restrict__ Wv) {
    __shared__ float tile[32][33];
    int z = blockIdx.z;
    const float* W = (z == 0) ? Wq : ((z == 1) ? Wk : Wv);
    int nb = blockIdx.x * 32, kb = blockIdx.y * 32;
    int tx = threadIdx.x, ty = threadIdx.y;  // 32 x 8
#pragma unroll
    for (int r = 0; r < 32; r += 8)
        tile[ty + r][tx] = W[(size_t)(kb + ty + r) * CDIM + nb + tx];
    __syncthreads();
    uint32_t* outw = g_wt + (size_t)z * CDIM * CDIM;
#pragma unroll
    for (int r = 0; r < 32; r += 8) {
        int n = nb + ty + r;
        int k = kb + tx;
        outw[(size_t)n * CDIM + kperm(k)] = f2tf(tile[tx][ty + r]);
    }
}

// ---------------------------------------------------------------------------
// QKV GEMM (tf32 mma, 3-stage cp.async, XOR-swizzled smem, 1 sync/iter).
// CTA 128x128, BK=32, **128 threads, 4 warps, warp tile 64x64** (2x2 grid).
// 16 LDS.64 feed 32 MMAs per ks -> 128 smem-B/MMA (was 192).
// smem tile: 128 rows x 32 words, word = r*32 + 8*((c>>3)^(r&3)) + (c&7)
// grid = (768/128=6, 3, 32768/128=256)
// ---------------------------------------------------------------------------
#define TWORDS (128 * 32)              // 4096 words per operand tile
#define STGW   (2 * TWORDS)            // A + B per stage (words) = 8192
#define NSTG   3
#define QSMEM  (NSTG * STGW * 4)       // 98304 bytes
#define NKT    (CDIM / 32)             // 24

__device__ __forceinline__ void qkv_load_stage(uint32_t dst, const uint32_t* __restrict__ gak,
                                               const uint32_t* __restrict__ gbk, int tid) {
    const int r0 = tid >> 3;           // 0..15
    const int cb = (tid & 7) * 4;      // 0,4,...,28
#pragma unroll
    for (int i = 0; i < 8; i++) {
        int r = r0 + i * 16;
        uint32_t sw = (uint32_t)(r * 32 + (((cb >> 3) ^ (r & 3)) << 3) + (cb & 7)) * 4;
        CP16(dst + sw, gak + (size_t)r * CDIM + cb);
        CP16(dst + TWORDS * 4 + sw, gbk + (size_t)r * CDIM + cb);
    }
    CP_COMMIT();
}

__global__ void __launch_bounds__(128, 2) qkv_mma_kernel(const float* dummy) {
    extern __shared__ uint32_t sm[];
    const int z = blockIdx.y;
    const int m0 = blockIdx.z * 128;
    const int n0 = blockIdx.x * 128;
    const int tid = threadIdx.x;
    const int wid = tid >> 5, lane = tid & 31;
    const int wm = (wid & 1) * 64;
    const int wn = (wid >> 1) * 64;
    const int lr = lane >> 2, lc = lane & 3;
    const int lr3 = lr & 3;

    const uint32_t* __restrict__ ga = g_xt + (size_t)m0 * CDIM;
    const uint32_t* __restrict__ gb = g_wt + (size_t)z * CDIM * CDIM + (size_t)n0 * CDIM;
    const uint32_t sbase = smem_u32(sm);

    float acc[4][8][4] = {};

    // prologue: stages for kt=0,1
    qkv_load_stage(sbase, ga, gb, tid);
    qkv_load_stage(sbase + STGW * 4, ga + 32, gb + 32, tid);

    int cur = 0, wrt = 2;
    for (int kt = 0; kt < NKT; kt++) {
        if (kt == NKT - 1) { CP_WAIT0(); } else { CP_WAIT1(); }
        __syncthreads();

        if (kt + 2 < NKT) {
            qkv_load_stage(sbase + wrt * STGW * 4, ga + (kt + 2) * 32, gb + (kt + 2) * 32, tid);
            wrt = (wrt == 2) ? 0 : wrt + 1;
        }

        const uint32_t* As = sm + cur * STGW;
        const uint32_t* Bs = As + TWORDS;
        cur = (cur == 2) ? 0 : cur + 1;
#pragma unroll
        for (int ks = 0; ks < 4; ks++) {
            const int co = ((ks ^ lr3) << 3) + 2 * lc;   // swizzled col offset
            uint32_t a[4][4], b[8][2];
#pragma unroll
            for (int mi = 0; mi < 4; mi++) {
                int r = wm + mi * 16 + lr;
                uint2 p = *(const uint2*)(As + r * 32 + co);
                uint2 q = *(const uint2*)(As + (r + 8) * 32 + co);
                a[mi][0] = p.x; a[mi][1] = q.x; a[mi][2] = p.y; a[mi][3] = q.y;
            }
#pragma unroll
            for (int ni = 0; ni < 8; ni++) {
                uint2 bb = *(const uint2*)(Bs + (wn + ni * 8 + lr) * 32 + co);
                b[ni][0] = bb.x; b[ni][1] = bb.y;
            }
#pragma unroll
            for (int mi = 0; mi < 4; mi++)
#pragma unroll
                for (int ni = 0; ni < 8; ni++)
                    mma_tf32(acc[mi][ni], a[mi], b[ni]);
        }
    }

    // Epilogue. z<2: RoPE then write tf32 bits (k-permuted) to g_qt/g_kt.
    // z==2: write fp32 to g_v.
#pragma unroll
    for (int mi = 0; mi < 4; mi++) {
#pragma unroll
        for (int half = 0; half < 2; half++) {
            int r = m0 + wm + mi * 16 + lr + half * 8;
            int t = r & (TLEN - 1);
#pragma unroll
            for (int ni = 0; ni < 8; ni++) {
                float o0 = acc[mi][ni][half * 2 + 0];
                float o1 = acc[mi][ni][half * 2 + 1];
                int c = n0 + wn + ni * 8 + 2 * lc;
                if (z < 2) {
                    int j = c >> 1;
                    float cs = g_cos[t * HALF + j], sn = g_sin[t * HALF + j];
                    float p0 = o0 * cs - o1 * sn;
                    float p1 = o0 * sn + o1 * cs;
                    uint32_t* dst = (z == 0 ? g_qt : g_kt) + (size_t)r * CDIM;
                    dst[kperm(c)] = f2tf(p0);
                    dst[kperm(c + 1)] = f2tf(p1);
                } else {
                    *(float2*)(g_v + (size_t)r * CDIM + c) = make_float2(o0, o1);
                }
            }
        }
    }
}

// ---------------------------------------------------------------------------
// Scores (tf32 mma, cp.async double-buffer, LDS.64 fragments, padded layout).
// Inputs g_qt/g_kt are tf32 bits, d-permuted. CTA 64x64, BK=32, 128 threads.
// grid = (4, 4, 128), upper-triangular blocks skipped.
// ---------------------------------------------------------------------------
#define ASTR 40
#define SWORDS (64 * ASTR)             // 2560 words per tile
#define SBUF (2 * SWORDS)

__global__ void __launch_bounds__(128) scores_mma_kernel() {
    __shared__ uint32_t sm[2 * SBUF];  // 40960 bytes
    const int bj = blockIdx.x;
    const int bi = blockIdx.y;
    if (bj > bi) return;
    const int b = blockIdx.z;

    const uint32_t* __restrict__ gq = g_qt + ((size_t)b * TLEN + bi * 64) * CDIM;
    const uint32_t* __restrict__ gk = g_kt + ((size_t)b * TLEN + bj * 64) * CDIM;
    const uint32_t sbase = smem_u32(sm);

    const int tid = threadIdx.x;
    const int wid = tid >> 5, lane = tid & 31;
    const int wm = (wid & 1) * 32;
    const int wn = (wid >> 1) * 32;
    const int lr = lane >> 2, lc = lane & 3;

    const int ldr = tid >> 3;          // 0..15 (x4 iters -> 64 rows)
    const int ldc = (tid & 7) * 4;

    float acc[2][4][4] = {};

#pragma unroll
    for (int i = 0; i < 4; i++) {
        int r = ldr + i * 16;
        CP16(sbase + (r * ASTR + ldc) * 4, gq + (size_t)r * CDIM + ldc);
        CP16(sbase + (SWORDS + r * ASTR + ldc) * 4, gk + (size_t)r * CDIM + ldc);
    }
    CP_COMMIT();

    for (int kt = 0; kt < CDIM / 32; kt++) {
        if (kt + 1 < CDIM / 32) {
            uint32_t dbase = sbase + ((kt + 1) & 1) * SBUF * 4;
            const uint32_t* gqk = gq + (kt + 1) * 32;
            const uint32_t* gkk = gk + (kt + 1) * 32;
#pragma unroll
            for (int i = 0; i < 4; i++) {
                int r = ldr + i * 16;
                CP16(dbase + (r * ASTR + ldc) * 4, gqk + (size_t)r * CDIM + ldc);
                CP16(dbase + (SWORDS + r * ASTR + ldc) * 4, gkk + (size_t)r * CDIM + ldc);
            }
            CP_COMMIT();
            CP_WAIT1();
        } else {
            CP_WAIT0();
        }
        __syncthreads();

        const uint32_t* Qs = sm + (kt & 1) * SBUF;
        const uint32_t* Ks = Qs + SWORDS;
#pragma unroll
        for (int ks = 0; ks < 4; ks++) {
            uint32_t a[2][4], bfr[4][2];
#pragma unroll
            for (int mi = 0; mi < 2; mi++) {
                int r = wm + mi * 16 + lr;
                uint2 p = *(const uint2*)(Qs + r * ASTR + ks * 8 + 2 * lc);
                uint2 q = *(const uint2*)(Qs + (r + 8) * ASTR + ks * 8 + 2 * lc);
                a[mi][0] = p.x; a[mi][1] = q.x; a[mi][2] = p.y; a[mi][3] = q.y;
            }
#pragma unroll
            for (int ni = 0; ni < 4; ni++) {
                uint2 bb = *(const uint2*)(Ks + (wn + ni * 8 + lr) * ASTR + ks * 8 + 2 * lc);
                bfr[ni][0] = bb.x; bfr[ni][1] = bb.y;
            }
#pragma unroll
            for (int mi = 0; mi < 2; mi++)
#pragma unroll
                for (int ni = 0; ni < 4; ni++)
                    mma_tf32(acc[mi][ni], a[mi], bfr[ni]);
        }
        __syncthreads();
    }

    const float scale = 0.03608439182435161f;   // 768^-0.5
    float* __restrict__ Sp = g_S + (size_t)b * TLEN * TLEN;
#pragma unroll
    for (int mi = 0; mi < 2; mi++)
#pragma unroll
        for (int half = 0; half < 2; half++) {
            int r = bi * 64 + wm + mi * 16 + lr + half * 8;
#pragma unroll
            for (int ni = 0; ni < 4; ni++) {
                int c = bj * 64 + wn + ni * 8 + 2 * lc;
                *(float2*)(Sp + (size_t)r * TLEN + c) =
                    make_float2(acc[mi][ni][half * 2] * scale, acc[mi][ni][half * 2 + 1] * scale);
            }
        }
}

// ---------------------------------------------------------------------------
// Softmax in place: one warp per (b, i) row; masks j > i, writes full row.
// ---------------------------------------------------------------------------
__global__ void __launch_bounds__(256) softmax_kernel() {
    const int gwarp = (blockIdx.x * blockDim.x + threadIdx.x) >> 5;
    const int lane = threadIdx.x & 31;
    const int b = gwarp >> 8;
    const int i = gwarp & 255;

    float* __restrict__ row = g_S + (size_t)b * TLEN * TLEN + (size_t)i * TLEN;

    float v[8];
    float m = -CUDART_INF_F;
#pragma unroll
    for (int r = 0; r < 8; r++) {
        int j = lane + 32 * r;
        v[r] = (j <= i) ? row[j] : -CUDART_INF_F;
        m = fmaxf(m, v[r]);
    }
#pragma unroll
    for (int off = 16; off > 0; off >>= 1)
        m = fmaxf(m, __shfl_xor_sync(0xFFFFFFFFu, m, off));

    float sum = 0.0f;
#pragma unroll
    for (int r = 0; r < 8; r++) {
        float p = expf(v[r] - m);
        v[r] = p;
        sum += p;
    }
#pragma unroll
    for (int off = 16; off > 0; off >>= 1)
        sum += __shfl_xor_sync(0xFFFFFFFFu, sum, off);

    const float inv = 1.0f / sum;
#pragma unroll
    for (int r = 0; r < 8; r++)
        row[lane + 32 * r] = v[r] * inv;
}

// ---------------------------------------------------------------------------
// PV (tf32 mma): out[b] = P[b] @ V[b], causal K truncation.
// CTA 64x64, BK=32, 128 threads. grid = (12, 4, 128).
// ---------------------------------------------------------------------------
__global__ void __launch_bounds__(128) pv_mma_kernel(float* __restrict__ out) {
    const int bn = blockIdx.x;
    const int bm = blockIdx.y;
    const int b = blockIdx.z;

    __shared__ uint32_t Ps[64][36];
    __shared__ uint32_t Vs[32][72];

    const float* __restrict__ P = g_S + (size_t)b * TLEN * TLEN;
    const float* __restrict__ V = g_v + (size_t)b * TLEN * CDIM;

    const int tid = threadIdx.x;
    const int wid = tid >> 5, lane = tid & 31;
    const int wm = (wid & 1) * 32;
    const int wn = (wid >> 1) * 32;
    const int lr = lane >> 2, lc = lane & 3;

    float acc[2][4][4] = {};
    const int nchunk = (bm + 1) * 2;

    for (int kt = 0; kt < nchunk; kt++) {
        float4 pv[4], vv[4];
#pragma unroll
        for (int i = 0; i < 4; i++) {
            int f = tid + i * 128;
            pv[i] = *(const float4*)(P + (size_t)(bm * 64 + (f >> 3)) * TLEN + kt * 32 + (f & 7) * 4);
            vv[i] = *(const float4*)(V + (size_t)(kt * 32 + (f >> 4)) * CDIM + bn * 64 + (f & 15) * 4);
        }
        __syncthreads();
#pragma unroll
        for (int i = 0; i < 4; i++) {
            int f = tid + i * 128;
            int pr = f >> 3, pc = (f & 7) * 4;
            Ps[pr][pc + 0] = f2tf(pv[i].x); Ps[pr][pc + 1] = f2tf(pv[i].y);
            Ps[pr][pc + 2] = f2tf(pv[i].z); Ps[pr][pc + 3] = f2tf(pv[i].w);
            int vr = f >> 4, vc = (f & 15) * 4;
            Vs[vr][vc + 0] = f2tf(vv[i].x); Vs[vr][vc + 1] = f2tf(vv[i].y);
            Vs[vr][vc + 2] = f2tf(vv[i].z); Vs[vr][vc + 3] = f2tf(vv[i].w);
        }
        __syncthreads();
#pragma unroll
        for (int ks = 0; ks < 4; ks++) {
            uint32_t a[2][4], bfr[4][2];
#pragma unroll
            for (int mi = 0; mi < 2; mi++) {
                int r = wm + mi * 16 + lr;
                a[mi][0] = Ps[r][ks * 8 + lc];
                a[mi][1] = Ps[r + 8][ks * 8 + lc];
                a[mi][2] = Ps[r][ks * 8 + lc + 4];
                a[mi][3] = Ps[r + 8][ks * 8 + lc + 4];
            }
#pragma unroll
            for (int ni = 0; ni < 4; ni++) {
                int c = wn + ni * 8 + lr;
                bfr[ni][0] = Vs[ks * 8 + lc][c];
                bfr[ni][1] = Vs[ks * 8 + lc + 4][c];
            }
#pragma unroll
            for (int mi = 0; mi < 2; mi++)
#pragma unroll
                for (int ni = 0; ni < 4; ni++)
                    mma_tf32(acc[mi][ni], a[mi], bfr[ni]);
        }
    }

    float* __restrict__ op = out + (size_t)b * TLEN * CDIM;
#pragma unroll
    for (int mi = 0; mi < 2; mi++)
#pragma unroll
        for (int half = 0; half < 2; half++) {
            int r = bm * 64 + wm + mi * 16 + lr + half * 8;
#pragma unroll
            for (int ni = 0; ni < 4; ni++) {
                int c = bn * 64 + wn + ni * 8 + 2 * lc;
                *(float2*)(op + (size_t)r * CDIM + c) =
                    make_float2(acc[mi][ni][half * 2], acc[mi][ni][half * 2 + 1]);
            }
        }
}

// ---------------------------------------------------------------------------
extern "C" void kernel_launch(void* const* d_in, const int* in_sizes, int n_in,
                              void* d_out, int out_size) {
    const float* x  = (const float*)d_in[0];
    const float* Wq = (const float*)d_in[1];
    const float* Wk = (const float*)d_in[2];
    const float* Wv = (const float*)d_in[3];
    float* out = (float*)d_out;

    cudaFuncSetAttribute(qkv_mma_kernel, cudaFuncAttributeMaxDynamicSharedMemorySize, QSMEM);

    rope_table_kernel<<<(TLEN * HALF + 255) / 256, 256>>>();
    convert_x_kernel<<<(int)((size_t)MROWS * CDIM / 8 / 256), 256>>>(x);
    convert_w_kernel<<<dim3(CDIM / 32, CDIM / 32, 3), dim3(32, 8)>>>(Wq, Wk, Wv);
    qkv_mma_kernel<<<dim3(CDIM / 128, 3, MROWS / 128), 128, QSMEM>>>(x);
    scores_mma_kernel<<<dim3(TLEN / 64, TLEN / 64, BATCH), 128>>>();
    softmax_kernel<<<(MROWS * 32) / 256, 256>>>();
    pv_mma_kernel<<<dim3(CDIM / 64, TLEN / 64, BATCH), 128>>>(out);
}

// round 8
// speedup vs baseline: 1.1849x; 1.1849x over previous
#include <cuda_runtime.h>
#include <cuda_fp16.h>
#include <math_constants.h>
#include <cstdint>

// Problem constants
#define BATCH 128
#define TLEN  256
#define CDIM  768
#define MROWS (BATCH * TLEN)     // 32768
#define HALF  (CDIM / 2)         // 384

// ---------------------------------------------------------------------------
// Device-global scratch.
// fp16 arrays (QKV inputs) use kperm16: within each 16-k group, pair p=(k>>1)&7
// goes to position ((p&3)<<1)|((p>>2)&1), element keeps k&1.
// tf32 arrays (scores inputs) use kperm8 as before.
// ---------------------------------------------------------------------------
__device__ __align__(256) __half    g_xh[(size_t)MROWS * CDIM];         // x, fp16 perm16
__device__ __align__(256) __half    g_wh[(size_t)3 * CDIM * CDIM];      // W^T [z][n][k], fp16 perm16
__device__ __align__(256) uint32_t  g_qt[(size_t)MROWS * CDIM];         // q (RoPE'd), tf32 perm8
__device__ __align__(256) uint32_t  g_kt[(size_t)MROWS * CDIM];         // k (RoPE'd), tf32 perm8
__device__ __align__(256) float     g_v[(size_t)MROWS * CDIM];          // v, fp32
__device__ __align__(256) float     g_S[(size_t)BATCH * TLEN * TLEN];
__device__ __align__(256) float     g_cos[TLEN * HALF];
__device__ __align__(256) float     g_sin[TLEN * HALF];

// ---------------------------------------------------------------------------
// Helpers
// ---------------------------------------------------------------------------
__device__ __forceinline__ uint32_t f2tf(float f) {
    uint32_t r;
    asm("cvt.rna.tf32.f32 %0, %1;" : "=r"(r) : "f"(f));
    return r;
}
__device__ __forceinline__ uint32_t smem_u32(const void* p) {
    uint32_t a;
    asm("{ .reg .u64 t; cvta.to.shared.u64 t, %1; cvt.u32.u64 %0, t; }" : "=r"(a) : "l"(p));
    return a;
}
#define CP16(dst, src) asm volatile("cp.async.cg.shared.global [%0], [%1], 16;" :: "r"(dst), "l"(src))
#define CP_COMMIT()    asm volatile("cp.async.commit_group;" ::: "memory")
#define CP_WAIT1()     asm volatile("cp.async.wait_group 1;" ::: "memory")
#define CP_WAIT0()     asm volatile("cp.async.wait_group 0;" ::: "memory")

__device__ __forceinline__ void mma_tf32(float* d, const uint32_t* a, const uint32_t* b) {
    asm volatile(
        "mma.sync.aligned.m16n8k8.row.col.f32.tf32.tf32.f32 "
        "{%0,%1,%2,%3}, {%4,%5,%6,%7}, {%8,%9}, {%0,%1,%2,%3};"
        : "+f"(d[0]), "+f"(d[1]), "+f"(d[2]), "+f"(d[3])
        : "r"(a[0]), "r"(a[1]), "r"(a[2]), "r"(a[3]), "r"(b[0]), "r"(b[1]));
}

__device__ __forceinline__ void mma_f16(float* d, const uint32_t* a, const uint32_t* b) {
    asm volatile(
        "mma.sync.aligned.m16n8k16.row.col.f32.f16.f16.f32 "
        "{%0,%1,%2,%3}, {%4,%5,%6,%7}, {%8,%9}, {%0,%1,%2,%3};"
        : "+f"(d[0]), "+f"(d[1]), "+f"(d[2]), "+f"(d[3])
        : "r"(a[0]), "r"(a[1]), "r"(a[2]), "r"(a[3]), "r"(b[0]), "r"(b[1]));
}

__device__ __forceinline__ int kperm8(int k) {       // tf32: permute within 8-group
    return (k & ~7) | (((k & 3) << 1) | ((k >> 2) & 1));
}
__device__ __forceinline__ int kperm16(int k) {      // fp16: permute pairs within 16-group
    int p = (k >> 1) & 7;
    int pp = ((p & 3) << 1) | ((p >> 2) & 1);
    return (k & ~15) | (pp << 1) | (k & 1);
}

// ---------------------------------------------------------------------------
// RoPE tables
// ---------------------------------------------------------------------------
__global__ void rope_table_kernel() {
    int idx = blockIdx.x * blockDim.x + threadIdx.x;
    if (idx >= TLEN * HALF) return;
    int t = idx / HALF;
    int j = idx % HALF;
    float theta = expf(-2.0f * (float)j * (1.0f / 768.0f) * 9.210340371976184f);
    float ang = (float)t * theta;
    float s, c;
    sincosf(ang, &s, &c);
    g_cos[idx] = c;
    g_sin[idx] = s;
}

// ---------------------------------------------------------------------------
// Convert x -> fp16, kperm16. One thread per 16 consecutive k (32B out).
// ---------------------------------------------------------------------------
__global__ void convert_x_fp16_kernel(const float* __restrict__ x) {
    size_t base = ((size_t)blockIdx.x * blockDim.x + threadIdx.x) * 16;
    __half o[16];
#pragma unroll
    for (int q = 0; q < 4; q++) {
        float4 v = *(const float4*)(x + base + q * 4);
#pragma unroll
        for (int e = 0; e < 4; e++) {
            int k = q * 4 + e;
            float f = (e == 0) ? v.x : (e == 1) ? v.y : (e == 2) ? v.z : v.w;
            o[kperm16(k) & 15] = __float2half(f);
        }
    }
    *(uint4*)(g_xh + base) = *(uint4*)&o[0];
    *(uint4*)(g_xh + base + 8) = *(uint4*)&o[8];
}

// ---------------------------------------------------------------------------
// Convert W -> W^T [n][k], fp16, kperm16.
// ---------------------------------------------------------------------------
__global__ void convert_w_fp16_kernel(const float* __restrict__ Wq,
                                      const float* __restrict__ Wk,
                                      const float* __restrict__ Wv) {
    __shared__ float tile[32][33];
    int z = blockIdx.z;
    const float* W = (z == 0) ? Wq : ((z == 1) ? Wk : Wv);
    int nb = blockIdx.x * 32, kb = blockIdx.y * 32;
    int tx = threadIdx.x, ty = threadIdx.y;  // 32 x 8
#pragma unroll
    for (int r = 0; r < 32; r += 8)
        tile[ty + r][tx] = W[(size_t)(kb + ty + r) * CDIM + nb + tx];
    __syncthreads();
    __half* outw = g_wh + (size_t)z * CDIM * CDIM;
#pragma unroll
    for (int r = 0; r < 32; r += 8) {
        int n = nb + ty + r;
        int k = kb + tx;
        outw[(size_t)n * CDIM + kperm16(k)] = __float2half(tile[tx][ty + r]);
    }
}

// ---------------------------------------------------------------------------
// QKV GEMM (fp16 m16n8k16, fp32 acc, 3-stage cp.async, 1 sync/iter).
// CTA 128x128, BK=32 (2 k16 steps), 256 threads, warp tile 64x32 (2x4 grid).
// smem per operand tile: [2 ks][128 rows][32 B]; ks-block stride = 4096 B.
// grid = (768/128=6, 3, 32768/128=256)
// ---------------------------------------------------------------------------
#define KSB    4096                    // ks-block stride: 128 rows * 32 B
#define TBYTES (2 * KSB)               // 8192 B per operand tile
#define STGB   (2 * TBYTES)            // A + B per stage = 16384 B
#define NSTG   3
#define QSMEM  (NSTG * STGB)           // 49152 B
#define NKT    (CDIM / 32)             // 24

__device__ __forceinline__ void qkv_load_stage(uint32_t dst, const __half* __restrict__ gak,
                                               const __half* __restrict__ gbk, int tid) {
    // A: 512 16B-chunks, B: 512. 2 + 2 per thread.
#pragma unroll
    for (int i = 0; i < 2; i++) {
        int cid = tid + i * 256;
        int r = cid >> 2, rem = cid & 3;
        int kk = rem >> 1, c = rem & 1;           // ks block, chunk within 32B row
        uint32_t soff = (uint32_t)(kk * KSB + r * 32 + c * 16);
        size_t goff = (size_t)r * CDIM + kk * 16 + c * 8;
        CP16(dst + soff, gak + goff);
        CP16(dst + TBYTES + soff, gbk + goff);
    }
    CP_COMMIT();
}

__global__ void __launch_bounds__(256, 2) qkv_mma_kernel(const float* dummy) {
    extern __shared__ char smc[];
    const int z = blockIdx.y;
    const int m0 = blockIdx.z * 128;
    const int n0 = blockIdx.x * 128;
    const int tid = threadIdx.x;
    const int wid = tid >> 5, lane = tid & 31;
    const int wm = (wid & 1) * 64;
    const int wn = (wid >> 1) * 32;
    const int lr = lane >> 2, lc = lane & 3;

    const __half* __restrict__ ga = g_xh + (size_t)m0 * CDIM;
    const __half* __restrict__ gb = g_wh + (size_t)z * CDIM * CDIM + (size_t)n0 * CDIM;
    const uint32_t sbase = smem_u32(smc);

    float acc[4][4][4] = {};

    qkv_load_stage(sbase, ga, gb, tid);
    qkv_load_stage(sbase + STGB, ga + 32, gb + 32, tid);

    int cur = 0, wrt = 2;
    for (int kt = 0; kt < NKT; kt++) {
        if (kt == NKT - 1) { CP_WAIT0(); } else { CP_WAIT1(); }
        __syncthreads();

        if (kt + 2 < NKT) {
            qkv_load_stage(sbase + wrt * STGB, ga + (kt + 2) * 32, gb + (kt + 2) * 32, tid);
            wrt = (wrt == 2) ? 0 : wrt + 1;
        }

        const char* As = smc + cur * STGB;
        const char* Bs = As + TBYTES;
        cur = (cur == 2) ? 0 : cur + 1;
#pragma unroll
        for (int ks = 0; ks < 2; ks++) {
            uint32_t a[4][4], b[4][2];
#pragma unroll
            for (int mi = 0; mi < 4; mi++) {
                int r = wm + mi * 16 + lr;
                uint2 u = *(const uint2*)(As + ks * KSB + r * 32 + lc * 8);
                uint2 v = *(const uint2*)(As + ks * KSB + (r + 8) * 32 + lc * 8);
                a[mi][0] = u.x; a[mi][1] = v.x; a[mi][2] = u.y; a[mi][3] = v.y;
            }
#pragma unroll
            for (int ni = 0; ni < 4; ni++) {
                uint2 bb = *(const uint2*)(Bs + ks * KSB + (wn + ni * 8 + lr) * 32 + lc * 8);
                b[ni][0] = bb.x; b[ni][1] = bb.y;
            }
#pragma unroll
            for (int mi = 0; mi < 4; mi++)
#pragma unroll
                for (int ni = 0; ni < 4; ni++)
                    mma_f16(acc[mi][ni], a[mi], b[ni]);
        }
    }

    // Epilogue (same fragment layout as tf32 version).
#pragma unroll
    for (int mi = 0; mi < 4; mi++) {
#pragma unroll
        for (int half = 0; half < 2; half++) {
            int r = m0 + wm + mi * 16 + lr + half * 8;
            int t = r & (TLEN - 1);
#pragma unroll
            for (int ni = 0; ni < 4; ni++) {
                float o0 = acc[mi][ni][half * 2 + 0];
                float o1 = acc[mi][ni][half * 2 + 1];
                int c = n0 + wn + ni * 8 + 2 * lc;
                if (z < 2) {
                    int j = c >> 1;
                    float cs = g_cos[t * HALF + j], sn = g_sin[t * HALF + j];
                    float p0 = o0 * cs - o1 * sn;
                    float p1 = o0 * sn + o1 * cs;
                    uint32_t* dst = (z == 0 ? g_qt : g_kt) + (size_t)r * CDIM;
                    dst[kperm8(c)] = f2tf(p0);
                    dst[kperm8(c + 1)] = f2tf(p1);
                } else {
                    *(float2*)(g_v + (size_t)r * CDIM + c) = make_float2(o0, o1);
                }
            }
        }
    }
}

// ---------------------------------------------------------------------------
// Scores (tf32 mma, cp.async double-buffer, LDS.64, padded layout) — unchanged.
// ---------------------------------------------------------------------------
#define ASTR 40
#define SWORDS (64 * ASTR)             // 2560 words per tile
#define SBUF (2 * SWORDS)

__global__ void __launch_bounds__(128) scores_mma_kernel() {
    __shared__ uint32_t sm[2 * SBUF];  // 40960 bytes
    const int bj = blockIdx.x;
    const int bi = blockIdx.y;
    if (bj > bi) return;
    const int b = blockIdx.z;

    const uint32_t* __restrict__ gq = g_qt + ((size_t)b * TLEN + bi * 64) * CDIM;
    const uint32_t* __restrict__ gk = g_kt + ((size_t)b * TLEN + bj * 64) * CDIM;
    const uint32_t sbase = smem_u32(sm);

    const int tid = threadIdx.x;
    const int wid = tid >> 5, lane = tid & 31;
    const int wm = (wid & 1) * 32;
    const int wn = (wid >> 1) * 32;
    const int lr = lane >> 2, lc = lane & 3;

    const int ldr = tid >> 3;
    const int ldc = (tid & 7) * 4;

    float acc[2][4][4] = {};

#pragma unroll
    for (int i = 0; i < 4; i++) {
        int r = ldr + i * 16;
        CP16(sbase + (r * ASTR + ldc) * 4, gq + (size_t)r * CDIM + ldc);
        CP16(sbase + (SWORDS + r * ASTR + ldc) * 4, gk + (size_t)r * CDIM + ldc);
    }
    CP_COMMIT();

    for (int kt = 0; kt < CDIM / 32; kt++) {
        if (kt + 1 < CDIM / 32) {
            uint32_t dbase = sbase + ((kt + 1) & 1) * SBUF * 4;
            const uint32_t* gqk = gq + (kt + 1) * 32;
            const uint32_t* gkk = gk + (kt + 1) * 32;
#pragma unroll
            for (int i = 0; i < 4; i++) {
                int r = ldr + i * 16;
                CP16(dbase + (r * ASTR + ldc) * 4, gqk + (size_t)r * CDIM + ldc);
                CP16(dbase + (SWORDS + r * ASTR + ldc) * 4, gkk + (size_t)r * CDIM + ldc);
            }
            CP_COMMIT();
            CP_WAIT1();
        } else {
            CP_WAIT0();
        }
        __syncthreads();

        const uint32_t* Qs = sm + (kt & 1) * SBUF;
        const uint32_t* Ks = Qs + SWORDS;
#pragma unroll
        for (int ks = 0; ks < 4; ks++) {
            uint32_t a[2][4], bfr[4][2];
#pragma unroll
            for (int mi = 0; mi < 2; mi++) {
                int r = wm + mi * 16 + lr;
                uint2 p = *(const uint2*)(Qs + r * ASTR + ks * 8 + 2 * lc);
                uint2 q = *(const uint2*)(Qs + (r + 8) * ASTR + ks * 8 + 2 * lc);
                a[mi][0] = p.x; a[mi][1] = q.x; a[mi][2] = p.y; a[mi][3] = q.y;
            }
#pragma unroll
            for (int ni = 0; ni < 4; ni++) {
                uint2 bb = *(const uint2*)(Ks + (wn + ni * 8 + lr) * ASTR + ks * 8 + 2 * lc);
                bfr[ni][0] = bb.x; bfr[ni][1] = bb.y;
            }
#pragma unroll
            for (int mi = 0; mi < 2; mi++)
#pragma unroll
                for (int ni = 0; ni < 4; ni++)
                    mma_tf32(acc[mi][ni], a[mi], bfr[ni]);
        }
        __syncthreads();
    }

    const float scale = 0.03608439182435161f;   // 768^-0.5
    float* __restrict__ Sp = g_S + (size_t)b * TLEN * TLEN;
#pragma unroll
    for (int mi = 0; mi < 2; mi++)
#pragma unroll
        for (int half = 0; half < 2; half++) {
            int r = bi * 64 + wm + mi * 16 + lr + half * 8;
#pragma unroll
            for (int ni = 0; ni < 4; ni++) {
                int c = bj * 64 + wn + ni * 8 + 2 * lc;
                *(float2*)(Sp + (size_t)r * TLEN + c) =
                    make_float2(acc[mi][ni][half * 2] * scale, acc[mi][ni][half * 2 + 1] * scale);
            }
        }
}

// ---------------------------------------------------------------------------
// Softmax in place — unchanged.
// ---------------------------------------------------------------------------
__global__ void __launch_bounds__(256) softmax_kernel() {
    const int gwarp = (blockIdx.x * blockDim.x + threadIdx.x) >> 5;
    const int lane = threadIdx.x & 31;
    const int b = gwarp >> 8;
    const int i = gwarp & 255;

    float* __restrict__ row = g_S + (size_t)b * TLEN * TLEN + (size_t)i * TLEN;

    float v[8];
    float m = -CUDART_INF_F;
#pragma unroll
    for (int r = 0; r < 8; r++) {
        int j = lane + 32 * r;
        v[r] = (j <= i) ? row[j] : -CUDART_INF_F;
        m = fmaxf(m, v[r]);
    }
#pragma unroll
    for (int off = 16; off > 0; off >>= 1)
        m = fmaxf(m, __shfl_xor_sync(0xFFFFFFFFu, m, off));

    float sum = 0.0f;
#pragma unroll
    for (int r = 0; r < 8; r++) {
        float p = expf(v[r] - m);
        v[r] = p;
        sum += p;
    }
#pragma unroll
    for (int off = 16; off > 0; off >>= 1)
        sum += __shfl_xor_sync(0xFFFFFFFFu, sum, off);

    const float inv = 1.0f / sum;
#pragma unroll
    for (int r = 0; r < 8; r++)
        row[lane + 32 * r] = v[r] * inv;
}

// ---------------------------------------------------------------------------
// PV (tf32 mma): out[b] = P[b] @ V[b], causal K truncation — unchanged.
// ---------------------------------------------------------------------------
__global__ void __launch_bounds__(128) pv_mma_kernel(float* __restrict__ out) {
    const int bn = blockIdx.x;
    const int bm = blockIdx.y;
    const int b = blockIdx.z;

    __shared__ uint32_t Ps[64][36];
    __shared__ uint32_t Vs[32][72];

    const float* __restrict__ P = g_S + (size_t)b * TLEN * TLEN;
    const float* __restrict__ V = g_v + (size_t)b * TLEN * CDIM;

    const int tid = threadIdx.x;
    const int wid = tid >> 5, lane = tid & 31;
    const int wm = (wid & 1) * 32;
    const int wn = (wid >> 1) * 32;
    const int lr = lane >> 2, lc = lane & 3;

    float acc[2][4][4] = {};
    const int nchunk = (bm + 1) * 2;

    for (int kt = 0; kt < nchunk; kt++) {
        float4 pv[4], vv[4];
#pragma unroll
        for (int i = 0; i < 4; i++) {
            int f = tid + i * 128;
            pv[i] = *(const float4*)(P + (size_t)(bm * 64 + (f >> 3)) * TLEN + kt * 32 + (f & 7) * 4);
            vv[i] = *(const float4*)(V + (size_t)(kt * 32 + (f >> 4)) * CDIM + bn * 64 + (f & 15) * 4);
        }
        __syncthreads();
#pragma unroll
        for (int i = 0; i < 4; i++) {
            int f = tid + i * 128;
            int pr = f >> 3, pc = (f & 7) * 4;
            Ps[pr][pc + 0] = f2tf(pv[i].x); Ps[pr][pc + 1] = f2tf(pv[i].y);
            Ps[pr][pc + 2] = f2tf(pv[i].z); Ps[pr][pc + 3] = f2tf(pv[i].w);
            int vr = f >> 4, vc = (f & 15) * 4;
            Vs[vr][vc + 0] = f2tf(vv[i].x); Vs[vr][vc + 1] = f2tf(vv[i].y);
            Vs[vr][vc + 2] = f2tf(vv[i].z); Vs[vr][vc + 3] = f2tf(vv[i].w);
        }
        __syncthreads();
#pragma unroll
        for (int ks = 0; ks < 4; ks++) {
            uint32_t a[2][4], bfr[4][2];
#pragma unroll
            for (int mi = 0; mi < 2; mi++) {
                int r = wm + mi * 16 + lr;
                a[mi][0] = Ps[r][ks * 8 + lc];
                a[mi][1] = Ps[r + 8][ks * 8 + lc];
                a[mi][2] = Ps[r][ks * 8 + lc + 4];
                a[mi][3] = Ps[r + 8][ks * 8 + lc + 4];
            }
#pragma unroll
            for (int ni = 0; ni < 4; ni++) {
                int c = wn + ni * 8 + lr;
                bfr[ni][0] = Vs[ks * 8 + lc][c];
                bfr[ni][1] = Vs[ks * 8 + lc + 4][c];
            }
#pragma unroll
            for (int mi = 0; mi < 2; mi++)
#pragma unroll
                for (int ni = 0; ni < 4; ni++)
                    mma_tf32(acc[mi][ni], a[mi], bfr[ni]);
        }
    }

    float* __restrict__ op = out + (size_t)b * TLEN * CDIM;
#pragma unroll
    for (int mi = 0; mi < 2; mi++)
#pragma unroll
        for (int half = 0; half < 2; half++) {
            int r = bm * 64 + wm + mi * 16 + lr + half * 8;
#pragma unroll
            for (int ni = 0; ni < 4; ni++) {
                int c = bn * 64 + wn + ni * 8 + 2 * lc;
                *(float2*)(op + (size_t)r * CDIM + c) =
                    make_float2(acc[mi][ni][half * 2], acc[mi][ni][half * 2 + 1]);
            }
        }
}

// ---------------------------------------------------------------------------
extern "C" void kernel_launch(void* const* d_in, const int* in_sizes, int n_in,
                              void* d_out, int out_size) {
    const float* x  = (const float*)d_in[0];
    const float* Wq = (const float*)d_in[1];
    const float* Wk = (const float*)d_in[2];
    const float* Wv = (const float*)d_in[3];
    float* out = (float*)d_out;

    cudaFuncSetAttribute(qkv_mma_kernel, cudaFuncAttributeMaxDynamicSharedMemorySize, QSMEM);

    rope_table_kernel<<<(TLEN * HALF + 255) / 256, 256>>>();
    convert_x_fp16_kernel<<<(int)((size_t)MROWS * CDIM / 16 / 256), 256>>>(x);
    convert_w_fp16_kernel<<<dim3(CDIM / 32, CDIM / 32, 3), dim3(32, 8)>>>(Wq, Wk, Wv);
    qkv_mma_kernel<<<dim3(CDIM / 128, 3, MROWS / 128), 256, QSMEM>>>(x);
    scores_mma_kernel<<<dim3(TLEN / 64, TLEN / 64, BATCH), 128>>>();
    softmax_kernel<<<(MROWS * 32) / 256, 256>>>();
    pv_mma_kernel<<<dim3(CDIM / 64, TLEN / 64, BATCH), 128>>>(out);
}

// round 9
// speedup vs baseline: 1.5249x; 1.2869x over previous
#include <cuda_runtime.h>
#include <cuda_fp16.h>
#include <math_constants.h>
#include <cstdint>

// Problem constants
#define BATCH 128
#define TLEN  256
#define CDIM  768
#define MROWS (BATCH * TLEN)     // 32768
#define HALF  (CDIM / 2)         // 384

// ---------------------------------------------------------------------------
// Device-global scratch.
// fp16 arrays (QKV inputs): PLAIN k-order (ldmatrix gives canonical frags).
// tf32 arrays (scores inputs) use kperm8.
// ---------------------------------------------------------------------------
__device__ __align__(256) __half    g_xh[(size_t)MROWS * CDIM];         // x, fp16
__device__ __align__(256) __half    g_wh[(size_t)3 * CDIM * CDIM];      // W^T [z][n][k], fp16
__device__ __align__(256) uint32_t  g_qt[(size_t)MROWS * CDIM];         // q (RoPE'd), tf32 perm8
__device__ __align__(256) uint32_t  g_kt[(size_t)MROWS * CDIM];         // k (RoPE'd), tf32 perm8
__device__ __align__(256) float     g_v[(size_t)MROWS * CDIM];          // v, fp32
__device__ __align__(256) float     g_S[(size_t)BATCH * TLEN * TLEN];
__device__ __align__(256) float     g_cos[TLEN * HALF];
__device__ __align__(256) float     g_sin[TLEN * HALF];

// ---------------------------------------------------------------------------
// Helpers
// ---------------------------------------------------------------------------
__device__ __forceinline__ uint32_t f2tf(float f) {
    uint32_t r;
    asm("cvt.rna.tf32.f32 %0, %1;" : "=r"(r) : "f"(f));
    return r;
}
__device__ __forceinline__ uint32_t smem_u32(const void* p) {
    uint32_t a;
    asm("{ .reg .u64 t; cvta.to.shared.u64 t, %1; cvt.u32.u64 %0, t; }" : "=r"(a) : "l"(p));
    return a;
}
#define CP16(dst, src) asm volatile("cp.async.cg.shared.global [%0], [%1], 16;" :: "r"(dst), "l"(src))
#define CP_COMMIT()    asm volatile("cp.async.commit_group;" ::: "memory")
#define CP_WAIT1()     asm volatile("cp.async.wait_group 1;" ::: "memory")
#define CP_WAIT0()     asm volatile("cp.async.wait_group 0;" ::: "memory")

#define LDSM4(r0, r1, r2, r3, addr) \
    asm volatile("ldmatrix.sync.aligned.m8n8.x4.shared.b16 {%0,%1,%2,%3}, [%4];" \
        : "=r"(r0), "=r"(r1), "=r"(r2), "=r"(r3) : "r"(addr))

__device__ __forceinline__ void mma_tf32(float* d, const uint32_t* a, const uint32_t* b) {
    asm volatile(
        "mma.sync.aligned.m16n8k8.row.col.f32.tf32.tf32.f32 "
        "{%0,%1,%2,%3}, {%4,%5,%6,%7}, {%8,%9}, {%0,%1,%2,%3};"
        : "+f"(d[0]), "+f"(d[1]), "+f"(d[2]), "+f"(d[3])
        : "r"(a[0]), "r"(a[1]), "r"(a[2]), "r"(a[3]), "r"(b[0]), "r"(b[1]));
}

__device__ __forceinline__ void mma_f16(float* d, const uint32_t* a, const uint32_t* b) {
    asm volatile(
        "mma.sync.aligned.m16n8k16.row.col.f32.f16.f16.f32 "
        "{%0,%1,%2,%3}, {%4,%5,%6,%7}, {%8,%9}, {%0,%1,%2,%3};"
        : "+f"(d[0]), "+f"(d[1]), "+f"(d[2]), "+f"(d[3])
        : "r"(a[0]), "r"(a[1]), "r"(a[2]), "r"(a[3]), "r"(b[0]), "r"(b[1]));
}

__device__ __forceinline__ int kperm8(int k) {       // tf32: permute within 8-group
    return (k & ~7) | (((k & 3) << 1) | ((k >> 2) & 1));
}

// ---------------------------------------------------------------------------
// RoPE tables
// ---------------------------------------------------------------------------
__global__ void rope_table_kernel() {
    int idx = blockIdx.x * blockDim.x + threadIdx.x;
    if (idx >= TLEN * HALF) return;
    int t = idx / HALF;
    int j = idx % HALF;
    float theta = expf(-2.0f * (float)j * (1.0f / 768.0f) * 9.210340371976184f);
    float ang = (float)t * theta;
    float s, c;
    sincosf(ang, &s, &c);
    g_cos[idx] = c;
    g_sin[idx] = s;
}

// ---------------------------------------------------------------------------
// Convert x -> fp16 (plain order). One thread per 8 consecutive elements.
// ---------------------------------------------------------------------------
__global__ void convert_x_fp16_kernel(const float* __restrict__ x) {
    size_t base = ((size_t)blockIdx.x * blockDim.x + threadIdx.x) * 8;
    float4 v0 = *(const float4*)(x + base);
    float4 v1 = *(const float4*)(x + base + 4);
    __half2 h[4];
    h[0] = __floats2half2_rn(v0.x, v0.y);
    h[1] = __floats2half2_rn(v0.z, v0.w);
    h[2] = __floats2half2_rn(v1.x, v1.y);
    h[3] = __floats2half2_rn(v1.z, v1.w);
    *(uint4*)(g_xh + base) = *(uint4*)h;
}

// ---------------------------------------------------------------------------
// Convert W -> W^T [n][k], fp16 (plain order).
// ---------------------------------------------------------------------------
__global__ void convert_w_fp16_kernel(const float* __restrict__ Wq,
                                      const float* __restrict__ Wk,
                                      const float* __restrict__ Wv) {
    __shared__ float tile[32][33];
    int z = blockIdx.z;
    const float* W = (z == 0) ? Wq : ((z == 1) ? Wk : Wv);
    int nb = blockIdx.x * 32, kb = blockIdx.y * 32;
    int tx = threadIdx.x, ty = threadIdx.y;  // 32 x 8
#pragma unroll
    for (int r = 0; r < 32; r += 8)
        tile[ty + r][tx] = W[(size_t)(kb + ty + r) * CDIM + nb + tx];
    __syncthreads();
    __half* outw = g_wh + (size_t)z * CDIM * CDIM;
#pragma unroll
    for (int r = 0; r < 32; r += 8) {
        int n = nb + ty + r;
        outw[(size_t)n * CDIM + kb + tx] = __float2half(tile[tx][ty + r]);
    }
}

// ---------------------------------------------------------------------------
// QKV GEMM (fp16 m16n8k16 + ldmatrix, BK=64, 3-stage cp.async, 1 sync/iter).
// CTA 128x128, 256 threads, warp tile 64x32 (2x4 grid).
// smem per operand tile: 128 rows x 128B (8 chunks of 16B), chunk ^= (r&7).
// grid = (768/128=6, 3, 32768/128=256)
// ---------------------------------------------------------------------------
#define TILEB  (128 * 128)             // 16384 B per operand tile
#define STGB   (2 * TILEB)             // A + B per stage = 32768 B
#define NSTG   3
#define QSMEM  (NSTG * STGB)           // 98304 B
#define NKT    (CDIM / 64)             // 12

__device__ __forceinline__ void qkv_load_stage(uint32_t dst, const __half* __restrict__ gak,
                                               const __half* __restrict__ gbk, int tid) {
    // per operand: 128 rows x 8 chunks = 1024 chunks; 4 per thread.
#pragma unroll
    for (int i = 0; i < 4; i++) {
        int cid = tid + i * 256;
        int r = cid >> 3, c = cid & 7;
        uint32_t soff = (uint32_t)(r * 128 + ((c ^ (r & 7)) << 4));
        size_t goff = (size_t)r * CDIM + c * 8;
        CP16(dst + soff, gak + goff);
        CP16(dst + TILEB + soff, gbk + goff);
    }
    CP_COMMIT();
}

__global__ void __launch_bounds__(256, 2) qkv_mma_kernel(const float* dummy) {
    extern __shared__ char smc[];
    const int z = blockIdx.y;
    const int m0 = blockIdx.z * 128;
    const int n0 = blockIdx.x * 128;
    const int tid = threadIdx.x;
    const int wid = tid >> 5, lane = tid & 31;
    const int wm = (wid & 1) * 64;
    const int wn = (wid >> 1) * 32;
    const int lr = lane >> 2, lc = lane & 3;

    const __half* __restrict__ ga = g_xh + (size_t)m0 * CDIM;
    const __half* __restrict__ gb = g_wh + (size_t)z * CDIM * CDIM + (size_t)n0 * CDIM;
    const uint32_t sbase = smem_u32(smc);

    // ldmatrix per-lane row indices (canonical m8n8 quad layout)
    const int l7 = lane & 7;
    const int rowA[4] = { wm + 0 * 16 + ((lane >> 3) & 1) * 8 + l7,
                          wm + 1 * 16 + ((lane >> 3) & 1) * 8 + l7,
                          wm + 2 * 16 + ((lane >> 3) & 1) * 8 + l7,
                          wm + 3 * 16 + ((lane >> 3) & 1) * 8 + l7 };
    const int kbitA = (lane >> 4) & 1;            // matrices 2,3 -> k+8 chunk
    const int rowB[2] = { wn + 0 * 16 + ((lane >> 4) & 1) * 8 + l7,
                          wn + 1 * 16 + ((lane >> 4) & 1) * 8 + l7 };
    const int kbitB = (lane >> 3) & 1;            // matrices 1,3 -> k+8 chunk

    float acc[4][4][4] = {};

    qkv_load_stage(sbase, ga, gb, tid);
    qkv_load_stage(sbase + STGB, ga + 64, gb + 64, tid);

    int cur = 0, wrt = 2;
    for (int kt = 0; kt < NKT; kt++) {
        if (kt == NKT - 1) { CP_WAIT0(); } else { CP_WAIT1(); }
        __syncthreads();

        if (kt + 2 < NKT) {
            qkv_load_stage(sbase + wrt * STGB, ga + (kt + 2) * 64, gb + (kt + 2) * 64, tid);
            wrt = (wrt == 2) ? 0 : wrt + 1;
        }

        const uint32_t As = sbase + cur * STGB;
        const uint32_t Bs = As + TILEB;
        cur = (cur == 2) ? 0 : cur + 1;

#pragma unroll
        for (int ks = 0; ks < 4; ks++) {
            uint32_t a[4][4], b[4][2];
#pragma unroll
            for (int mi = 0; mi < 4; mi++) {
                int r = rowA[mi];
                uint32_t addr = As + r * 128 + (((2 * ks + kbitA) ^ (r & 7)) << 4);
                LDSM4(a[mi][0], a[mi][1], a[mi][2], a[mi][3], addr);
            }
#pragma unroll
            for (int j = 0; j < 2; j++) {
                int r = rowB[j];
                uint32_t addr = Bs + r * 128 + (((2 * ks + kbitB) ^ (r & 7)) << 4);
                LDSM4(b[2 * j][0], b[2 * j][1], b[2 * j + 1][0], b[2 * j + 1][1], addr);
            }
#pragma unroll
            for (int mi = 0; mi < 4; mi++)
#pragma unroll
                for (int ni = 0; ni < 4; ni++)
                    mma_f16(acc[mi][ni], a[mi], b[ni]);
        }
    }

    // Epilogue. z<2: RoPE then write tf32 bits (kperm8) to g_qt/g_kt. z==2: fp32 v.
#pragma unroll
    for (int mi = 0; mi < 4; mi++) {
#pragma unroll
        for (int half = 0; half < 2; half++) {
            int r = m0 + wm + mi * 16 + lr + half * 8;
            int t = r & (TLEN - 1);
#pragma unroll
            for (int ni = 0; ni < 4; ni++) {
                float o0 = acc[mi][ni][half * 2 + 0];
                float o1 = acc[mi][ni][half * 2 + 1];
                int c = n0 + wn + ni * 8 + 2 * lc;
                if (z < 2) {
                    int j = c >> 1;
                    float cs = g_cos[t * HALF + j], sn = g_sin[t * HALF + j];
                    float p0 = o0 * cs - o1 * sn;
                    float p1 = o0 * sn + o1 * cs;
                    uint32_t* dst = (z == 0 ? g_qt : g_kt) + (size_t)r * CDIM;
                    dst[kperm8(c)] = f2tf(p0);
                    dst[kperm8(c + 1)] = f2tf(p1);
                } else {
                    *(float2*)(g_v + (size_t)r * CDIM + c) = make_float2(o0, o1);
                }
            }
        }
    }
}

// ---------------------------------------------------------------------------
// Scores (tf32 mma, cp.async double-buffer, LDS.64, padded layout) — unchanged.
// ---------------------------------------------------------------------------
#define ASTR 40
#define SWORDS (64 * ASTR)             // 2560 words per tile
#define SBUF (2 * SWORDS)

__global__ void __launch_bounds__(128) scores_mma_kernel() {
    __shared__ uint32_t sm[2 * SBUF];  // 40960 bytes
    const int bj = blockIdx.x;
    const int bi = blockIdx.y;
    if (bj > bi) return;
    const int b = blockIdx.z;

    const uint32_t* __restrict__ gq = g_qt + ((size_t)b * TLEN + bi * 64) * CDIM;
    const uint32_t* __restrict__ gk = g_kt + ((size_t)b * TLEN + bj * 64) * CDIM;
    const uint32_t sbase = smem_u32(sm);

    const int tid = threadIdx.x;
    const int wid = tid >> 5, lane = tid & 31;
    const int wm = (wid & 1) * 32;
    const int wn = (wid >> 1) * 32;
    const int lr = lane >> 2, lc = lane & 3;

    const int ldr = tid >> 3;
    const int ldc = (tid & 7) * 4;

    float acc[2][4][4] = {};

#pragma unroll
    for (int i = 0; i < 4; i++) {
        int r = ldr + i * 16;
        CP16(sbase + (r * ASTR + ldc) * 4, gq + (size_t)r * CDIM + ldc);
        CP16(sbase + (SWORDS + r * ASTR + ldc) * 4, gk + (size_t)r * CDIM + ldc);
    }
    CP_COMMIT();

    for (int kt = 0; kt < CDIM / 32; kt++) {
        if (kt + 1 < CDIM / 32) {
            uint32_t dbase = sbase + ((kt + 1) & 1) * SBUF * 4;
            const uint32_t* gqk = gq + (kt + 1) * 32;
            const uint32_t* gkk = gk + (kt + 1) * 32;
#pragma unroll
            for (int i = 0; i < 4; i++) {
                int r = ldr + i * 16;
                CP16(dbase + (r * ASTR + ldc) * 4, gqk + (size_t)r * CDIM + ldc);
                CP16(dbase + (SWORDS + r * ASTR + ldc) * 4, gkk + (size_t)r * CDIM + ldc);
            }
            CP_COMMIT();
            CP_WAIT1();
        } else {
            CP_WAIT0();
        }
        __syncthreads();

        const uint32_t* Qs = sm + (kt & 1) * SBUF;
        const uint32_t* Ks = Qs + SWORDS;
#pragma unroll
        for (int ks = 0; ks < 4; ks++) {
            uint32_t a[2][4], bfr[4][2];
#pragma unroll
            for (int mi = 0; mi < 2; mi++) {
                int r = wm + mi * 16 + lr;
                uint2 p = *(const uint2*)(Qs + r * ASTR + ks * 8 + 2 * lc);
                uint2 q = *(const uint2*)(Qs + (r + 8) * ASTR + ks * 8 + 2 * lc);
                a[mi][0] = p.x; a[mi][1] = q.x; a[mi][2] = p.y; a[mi][3] = q.y;
            }
#pragma unroll
            for (int ni = 0; ni < 4; ni++) {
                uint2 bb = *(const uint2*)(Ks + (wn + ni * 8 + lr) * ASTR + ks * 8 + 2 * lc);
                bfr[ni][0] = bb.x; bfr[ni][1] = bb.y;
            }
#pragma unroll
            for (int mi = 0; mi < 2; mi++)
#pragma unroll
                for (int ni = 0; ni < 4; ni++)
                    mma_tf32(acc[mi][ni], a[mi], bfr[ni]);
        }
        __syncthreads();
    }

    const float scale = 0.03608439182435161f;   // 768^-0.5
    float* __restrict__ Sp = g_S + (size_t)b * TLEN * TLEN;
#pragma unroll
    for (int mi = 0; mi < 2; mi++)
#pragma unroll
        for (int half = 0; half < 2; half++) {
            int r = bi * 64 + wm + mi * 16 + lr + half * 8;
#pragma unroll
            for (int ni = 0; ni < 4; ni++) {
                int c = bj * 64 + wn + ni * 8 + 2 * lc;
                *(float2*)(Sp + (size_t)r * TLEN + c) =
                    make_float2(acc[mi][ni][half * 2] * scale, acc[mi][ni][half * 2 + 1] * scale);
            }
        }
}

// ---------------------------------------------------------------------------
// Softmax in place — unchanged.
// ---------------------------------------------------------------------------
__global__ void __launch_bounds__(256) softmax_kernel() {
    const int gwarp = (blockIdx.x * blockDim.x + threadIdx.x) >> 5;
    const int lane = threadIdx.x & 31;
    const int b = gwarp >> 8;
    const int i = gwarp & 255;

    float* __restrict__ row = g_S + (size_t)b * TLEN * TLEN + (size_t)i * TLEN;

    float v[8];
    float m = -CUDART_INF_F;
#pragma unroll
    for (int r = 0; r < 8; r++) {
        int j = lane + 32 * r;
        v[r] = (j <= i) ? row[j] : -CUDART_INF_F;
        m = fmaxf(m, v[r]);
    }
#pragma unroll
    for (int off = 16; off > 0; off >>= 1)
        m = fmaxf(m, __shfl_xor_sync(0xFFFFFFFFu, m, off));

    float sum = 0.0f;
#pragma unroll
    for (int r = 0; r < 8; r++) {
        float p = expf(v[r] - m);
        v[r] = p;
        sum += p;
    }
#pragma unroll
    for (int off = 16; off > 0; off >>= 1)
        sum += __shfl_xor_sync(0xFFFFFFFFu, sum, off);

    const float inv = 1.0f / sum;
#pragma unroll
    for (int r = 0; r < 8; r++)
        row[lane + 32 * r] = v[r] * inv;
}

// ---------------------------------------------------------------------------
// PV (tf32 mma): out[b] = P[b] @ V[b], causal K truncation — unchanged.
// ---------------------------------------------------------------------------
__global__ void __launch_bounds__(128) pv_mma_kernel(float* __restrict__ out) {
    const int bn = blockIdx.x;
    const int bm = blockIdx.y;
    const int b = blockIdx.z;

    __shared__ uint32_t Ps[64][36];
    __shared__ uint32_t Vs[32][72];

    const float* __restrict__ P = g_S + (size_t)b * TLEN * TLEN;
    const float* __restrict__ V = g_v + (size_t)b * TLEN * CDIM;

    const int tid = threadIdx.x;
    const int wid = tid >> 5, lane = tid & 31;
    const int wm = (wid & 1) * 32;
    const int wn = (wid >> 1) * 32;
    const int lr = lane >> 2, lc = lane & 3;

    float acc[2][4][4] = {};
    const int nchunk = (bm + 1) * 2;

    for (int kt = 0; kt < nchunk; kt++) {
        float4 pv[4], vv[4];
#pragma unroll
        for (int i = 0; i < 4; i++) {
            int f = tid + i * 128;
            pv[i] = *(const float4*)(P + (size_t)(bm * 64 + (f >> 3)) * TLEN + kt * 32 + (f & 7) * 4);
            vv[i] = *(const float4*)(V + (size_t)(kt * 32 + (f >> 4)) * CDIM + bn * 64 + (f & 15) * 4);
        }
        __syncthreads();
#pragma unroll
        for (int i = 0; i < 4; i++) {
            int f = tid + i * 128;
            int pr = f >> 3, pc = (f & 7) * 4;
            Ps[pr][pc + 0] = f2tf(pv[i].x); Ps[pr][pc + 1] = f2tf(pv[i].y);
            Ps[pr][pc + 2] = f2tf(pv[i].z); Ps[pr][pc + 3] = f2tf(pv[i].w);
            int vr = f >> 4, vc = (f & 15) * 4;
            Vs[vr][vc + 0] = f2tf(vv[i].x); Vs[vr][vc + 1] = f2tf(vv[i].y);
            Vs[vr][vc + 2] = f2tf(vv[i].z); Vs[vr][vc + 3] = f2tf(vv[i].w);
        }
        __syncthreads();
#pragma unroll
        for (int ks = 0; ks < 4; ks++) {
            uint32_t a[2][4], bfr[4][2];
#pragma unroll
            for (int mi = 0; mi < 2; mi++) {
                int r = wm + mi * 16 + lr;
                a[mi][0] = Ps[r][ks * 8 + lc];
                a[mi][1] = Ps[r + 8][ks * 8 + lc];
                a[mi][2] = Ps[r][ks * 8 + lc + 4];
                a[mi][3] = Ps[r + 8][ks * 8 + lc + 4];
            }
#pragma unroll
            for (int ni = 0; ni < 4; ni++) {
                int c = wn + ni * 8 + lr;
                bfr[ni][0] = Vs[ks * 8 + lc][c];
                bfr[ni][1] = Vs[ks * 8 + lc + 4][c];
            }
#pragma unroll
            for (int mi = 0; mi < 2; mi++)
#pragma unroll
                for (int ni = 0; ni < 4; ni++)
                    mma_tf32(acc[mi][ni], a[mi], bfr[ni]);
        }
    }

    float* __restrict__ op = out + (size_t)b * TLEN * CDIM;
#pragma unroll
    for (int mi = 0; mi < 2; mi++)
#pragma unroll
        for (int half = 0; half < 2; half++) {
            int r = bm * 64 + wm + mi * 16 + lr + half * 8;
#pragma unroll
            for (int ni = 0; ni < 4; ni++) {
                int c = bn * 64 + wn + ni * 8 + 2 * lc;
                *(float2*)(op + (size_t)r * CDIM + c) =
                    make_float2(acc[mi][ni][half * 2], acc[mi][ni][half * 2 + 1]);
            }
        }
}

// ---------------------------------------------------------------------------
extern "C" void kernel_launch(void* const* d_in, const int* in_sizes, int n_in,
                              void* d_out, int out_size) {
    const float* x  = (const float*)d_in[0];
    const float* Wq = (const float*)d_in[1];
    const float* Wk = (const float*)d_in[2];
    const float* Wv = (const float*)d_in[3];
    float* out = (float*)d_out;

    cudaFuncSetAttribute(qkv_mma_kernel, cudaFuncAttributeMaxDynamicSharedMemorySize, QSMEM);

    rope_table_kernel<<<(TLEN * HALF + 255) / 256, 256>>>();
    convert_x_fp16_kernel<<<(int)((size_t)MROWS * CDIM / 8 / 256), 256>>>(x);
    convert_w_fp16_kernel<<<dim3(CDIM / 32, CDIM / 32, 3), dim3(32, 8)>>>(Wq, Wk, Wv);
    qkv_mma_kernel<<<dim3(CDIM / 128, 3, MROWS / 128), 256, QSMEM>>>(x);
    scores_mma_kernel<<<dim3(TLEN / 64, TLEN / 64, BATCH), 128>>>();
    softmax_kernel<<<(MROWS * 32) / 256, 256>>>();
    pv_mma_kernel<<<dim3(CDIM / 64, TLEN / 64, BATCH), 128>>>(out);
}

// round 10
// speedup vs baseline: 1.9466x; 1.2765x over previous
#include <cuda_runtime.h>
#include <cuda_fp16.h>
#include <math_constants.h>
#include <cstdint>

// Problem constants
#define BATCH 128
#define TLEN  256
#define CDIM  768
#define MROWS (BATCH * TLEN)     // 32768
#define HALF  (CDIM / 2)         // 384

// ---------------------------------------------------------------------------
// Device-global scratch (all fp16 operands in plain k-order; ldmatrix frags)
// ---------------------------------------------------------------------------
__device__ __align__(256) __half    g_xh[(size_t)MROWS * CDIM];         // x
__device__ __align__(256) __half    g_wh[(size_t)3 * CDIM * CDIM];      // W^T [z][n][k]
__device__ __align__(256) __half    g_qo[(size_t)MROWS * CDIM];         // q (RoPE'd)
__device__ __align__(256) __half    g_ko[(size_t)MROWS * CDIM];         // k (RoPE'd)
__device__ __align__(256) __half    g_vo[(size_t)MROWS * CDIM];         // v
__device__ __align__(256) float     g_S[(size_t)BATCH * TLEN * TLEN];   // scores fp32
__device__ __align__(256) __half    g_ph[(size_t)BATCH * TLEN * TLEN]; // probs fp16
__device__ __align__(256) float     g_cos[TLEN * HALF];
__device__ __align__(256) float     g_sin[TLEN * HALF];

// ---------------------------------------------------------------------------
// Helpers
// ---------------------------------------------------------------------------
__device__ __forceinline__ uint32_t smem_u32(const void* p) {
    uint32_t a;
    asm("{ .reg .u64 t; cvta.to.shared.u64 t, %1; cvt.u32.u64 %0, t; }" : "=r"(a) : "l"(p));
    return a;
}
#define CP16(dst, src) asm volatile("cp.async.cg.shared.global [%0], [%1], 16;" :: "r"(dst), "l"(src))
#define CP_COMMIT()    asm volatile("cp.async.commit_group;" ::: "memory")
#define CP_WAIT1()     asm volatile("cp.async.wait_group 1;" ::: "memory")
#define CP_WAIT0()     asm volatile("cp.async.wait_group 0;" ::: "memory")

#define LDSM4(r0, r1, r2, r3, addr) \
    asm volatile("ldmatrix.sync.aligned.m8n8.x4.shared.b16 {%0,%1,%2,%3}, [%4];" \
        : "=r"(r0), "=r"(r1), "=r"(r2), "=r"(r3) : "r"(addr))
#define LDSM4T(r0, r1, r2, r3, addr) \
    asm volatile("ldmatrix.sync.aligned.m8n8.x4.trans.shared.b16 {%0,%1,%2,%3}, [%4];" \
        : "=r"(r0), "=r"(r1), "=r"(r2), "=r"(r3) : "r"(addr))

__device__ __forceinline__ void mma_f16(float* d, const uint32_t* a, const uint32_t* b) {
    asm volatile(
        "mma.sync.aligned.m16n8k16.row.col.f32.f16.f16.f32 "
        "{%0,%1,%2,%3}, {%4,%5,%6,%7}, {%8,%9}, {%0,%1,%2,%3};"
        : "+f"(d[0]), "+f"(d[1]), "+f"(d[2]), "+f"(d[3])
        : "r"(a[0]), "r"(a[1]), "r"(a[2]), "r"(a[3]), "r"(b[0]), "r"(b[1]));
}

// ---------------------------------------------------------------------------
// RoPE tables
// ---------------------------------------------------------------------------
__global__ void rope_table_kernel() {
    int idx = blockIdx.x * blockDim.x + threadIdx.x;
    if (idx >= TLEN * HALF) return;
    int t = idx / HALF;
    int j = idx % HALF;
    float theta = expf(-2.0f * (float)j * (1.0f / 768.0f) * 9.210340371976184f);
    float ang = (float)t * theta;
    float s, c;
    sincosf(ang, &s, &c);
    g_cos[idx] = c;
    g_sin[idx] = s;
}

// ---------------------------------------------------------------------------
// Convert x -> fp16. One thread per 8 elements.
// ---------------------------------------------------------------------------
__global__ void convert_x_fp16_kernel(const float* __restrict__ x) {
    size_t base = ((size_t)blockIdx.x * blockDim.x + threadIdx.x) * 8;
    float4 v0 = *(const float4*)(x + base);
    float4 v1 = *(const float4*)(x + base + 4);
    __half2 h[4];
    h[0] = __floats2half2_rn(v0.x, v0.y);
    h[1] = __floats2half2_rn(v0.z, v0.w);
    h[2] = __floats2half2_rn(v1.x, v1.y);
    h[3] = __floats2half2_rn(v1.z, v1.w);
    *(uint4*)(g_xh + base) = *(uint4*)h;
}

// ---------------------------------------------------------------------------
// Convert W -> W^T [n][k], fp16.
// ---------------------------------------------------------------------------
__global__ void convert_w_fp16_kernel(const float* __restrict__ Wq,
                                      const float* __restrict__ Wk,
                                      const float* __restrict__ Wv) {
    __shared__ float tile[32][33];
    int z = blockIdx.z;
    const float* W = (z == 0) ? Wq : ((z == 1) ? Wk : Wv);
    int nb = blockIdx.x * 32, kb = blockIdx.y * 32;
    int tx = threadIdx.x, ty = threadIdx.y;  // 32 x 8
#pragma unroll
    for (int r = 0; r < 32; r += 8)
        tile[ty + r][tx] = W[(size_t)(kb + ty + r) * CDIM + nb + tx];
    __syncthreads();
    __half* outw = g_wh + (size_t)z * CDIM * CDIM;
#pragma unroll
    for (int r = 0; r < 32; r += 8) {
        int n = nb + ty + r;
        outw[(size_t)n * CDIM + kb + tx] = __float2half(tile[tx][ty + r]);
    }
}

// ---------------------------------------------------------------------------
// QKV GEMM (fp16 m16n8k16 + ldmatrix, BK=64, 3-stage cp.async).
// CTA 128x128, 256 threads, warp tile 64x32. grid = (6, 3, 256).
// smem per operand tile: 128 rows x 128B, chunk swizzle c ^= (r&7).
// ---------------------------------------------------------------------------
#define TILEB  (128 * 128)             // 16384 B per operand tile
#define STGB   (2 * TILEB)             // 32768 B per stage
#define NSTG   3
#define QSMEM  (NSTG * STGB)           // 98304 B
#define NKT    (CDIM / 64)             // 12

__device__ __forceinline__ void qkv_load_stage(uint32_t dst, const __half* __restrict__ gak,
                                               const __half* __restrict__ gbk, int tid) {
#pragma unroll
    for (int i = 0; i < 4; i++) {
        int cid = tid + i * 256;
        int r = cid >> 3, c = cid & 7;
        uint32_t soff = (uint32_t)(r * 128 + ((c ^ (r & 7)) << 4));
        size_t goff = (size_t)r * CDIM + c * 8;
        CP16(dst + soff, gak + goff);
        CP16(dst + TILEB + soff, gbk + goff);
    }
    CP_COMMIT();
}

__global__ void __launch_bounds__(256, 2) qkv_mma_kernel(const float* dummy) {
    extern __shared__ char smc[];
    const int z = blockIdx.y;
    const int m0 = blockIdx.z * 128;
    const int n0 = blockIdx.x * 128;
    const int tid = threadIdx.x;
    const int wid = tid >> 5, lane = tid & 31;
    const int wm = (wid & 1) * 64;
    const int wn = (wid >> 1) * 32;
    const int lr = lane >> 2, lc = lane & 3;

    const __half* __restrict__ ga = g_xh + (size_t)m0 * CDIM;
    const __half* __restrict__ gb = g_wh + (size_t)z * CDIM * CDIM + (size_t)n0 * CDIM;
    const uint32_t sbase = smem_u32(smc);

    const int l7 = lane & 7;
    const int rA = ((lane >> 3) & 1) * 8 + l7;
    const int kbitA = (lane >> 4) & 1;
    const int rB = ((lane >> 4) & 1) * 8 + l7;
    const int kbitB = (lane >> 3) & 1;

    float acc[4][4][4] = {};

    qkv_load_stage(sbase, ga, gb, tid);
    qkv_load_stage(sbase + STGB, ga + 64, gb + 64, tid);

    int cur = 0, wrt = 2;
    for (int kt = 0; kt < NKT; kt++) {
        if (kt == NKT - 1) { CP_WAIT0(); } else { CP_WAIT1(); }
        __syncthreads();

        if (kt + 2 < NKT) {
            qkv_load_stage(sbase + wrt * STGB, ga + (kt + 2) * 64, gb + (kt + 2) * 64, tid);
            wrt = (wrt == 2) ? 0 : wrt + 1;
        }

        const uint32_t As = sbase + cur * STGB;
        const uint32_t Bs = As + TILEB;
        cur = (cur == 2) ? 0 : cur + 1;

#pragma unroll
        for (int ks = 0; ks < 4; ks++) {
            uint32_t a[4][4], b[4][2];
#pragma unroll
            for (int mi = 0; mi < 4; mi++) {
                int r = wm + mi * 16 + rA;
                uint32_t addr = As + r * 128 + (((2 * ks + kbitA) ^ (r & 7)) << 4);
                LDSM4(a[mi][0], a[mi][1], a[mi][2], a[mi][3], addr);
            }
#pragma unroll
            for (int j = 0; j < 2; j++) {
                int r = wn + j * 16 + rB;
                uint32_t addr = Bs + r * 128 + (((2 * ks + kbitB) ^ (r & 7)) << 4);
                LDSM4(b[2 * j][0], b[2 * j][1], b[2 * j + 1][0], b[2 * j + 1][1], addr);
            }
#pragma unroll
            for (int mi = 0; mi < 4; mi++)
#pragma unroll
                for (int ni = 0; ni < 4; ni++)
                    mma_f16(acc[mi][ni], a[mi], b[ni]);
        }
    }

    // Epilogue. z<2: RoPE, write fp16 q/k. z==2: fp16 v.
    __half* const outz = (z == 0) ? g_qo : ((z == 1) ? g_ko : g_vo);
#pragma unroll
    for (int mi = 0; mi < 4; mi++) {
#pragma unroll
        for (int half = 0; half < 2; half++) {
            int r = m0 + wm + mi * 16 + lr + half * 8;
            int t = r & (TLEN - 1);
#pragma unroll
            for (int ni = 0; ni < 4; ni++) {
                float o0 = acc[mi][ni][half * 2 + 0];
                float o1 = acc[mi][ni][half * 2 + 1];
                int c = n0 + wn + ni * 8 + 2 * lc;
                if (z < 2) {
                    int j = c >> 1;
                    float cs = g_cos[t * HALF + j], sn = g_sin[t * HALF + j];
                    float p0 = o0 * cs - o1 * sn;
                    float p1 = o0 * sn + o1 * cs;
                    o0 = p0; o1 = p1;
                }
                *(__half2*)(outz + (size_t)r * CDIM + c) = __floats2half2_rn(o0, o1);
            }
        }
    }
}

// ---------------------------------------------------------------------------
// Scores (fp16 m16n8k16 + ldmatrix, BK=64, 3-stage cp.async).
// CTA 64x64, 128 threads, warp tile 32x32 (2x2). grid = (4,4,128), bj>bi skip.
// ---------------------------------------------------------------------------
#define STILEB (64 * 128)              // 8192 B per operand tile
#define SSTGB  (2 * STILEB)            // 16384 B per stage
#define SSMEM  (3 * SSTGB)             // 49152 B

__device__ __forceinline__ void sc_load_stage(uint32_t dst, const __half* __restrict__ gq,
                                              const __half* __restrict__ gk, int tid) {
#pragma unroll
    for (int i = 0; i < 4; i++) {
        int cid = tid + i * 128;
        int r = cid >> 3, c = cid & 7;
        uint32_t soff = (uint32_t)(r * 128 + ((c ^ (r & 7)) << 4));
        size_t goff = (size_t)r * CDIM + c * 8;
        CP16(dst + soff, gq + goff);
        CP16(dst + STILEB + soff, gk + goff);
    }
    CP_COMMIT();
}

__global__ void __launch_bounds__(128) scores_mma_kernel() {
    __shared__ char smc[SSMEM];
    const int bj = blockIdx.x;
    const int bi = blockIdx.y;
    if (bj > bi) return;
    const int b = blockIdx.z;

    const __half* __restrict__ gq = g_qo + ((size_t)b * TLEN + bi * 64) * CDIM;
    const __half* __restrict__ gk = g_ko + ((size_t)b * TLEN + bj * 64) * CDIM;
    const uint32_t sbase = smem_u32(smc);

    const int tid = threadIdx.x;
    const int wid = tid >> 5, lane = tid & 31;
    const int wm = (wid & 1) * 32;
    const int wn = (wid >> 1) * 32;
    const int lr = lane >> 2, lc = lane & 3;
    const int l7 = lane & 7;
    const int rA = ((lane >> 3) & 1) * 8 + l7;
    const int kbitA = (lane >> 4) & 1;
    const int rB = ((lane >> 4) & 1) * 8 + l7;
    const int kbitB = (lane >> 3) & 1;

    float acc[2][4][4] = {};

    sc_load_stage(sbase, gq, gk, tid);
    sc_load_stage(sbase + SSTGB, gq + 64, gk + 64, tid);

    int cur = 0, wrt = 2;
    for (int kt = 0; kt < NKT; kt++) {
        if (kt == NKT - 1) { CP_WAIT0(); } else { CP_WAIT1(); }
        __syncthreads();

        if (kt + 2 < NKT) {
            sc_load_stage(sbase + wrt * SSTGB, gq + (kt + 2) * 64, gk + (kt + 2) * 64, tid);
            wrt = (wrt == 2) ? 0 : wrt + 1;
        }

        const uint32_t Qs = sbase + cur * SSTGB;
        const uint32_t Ks = Qs + STILEB;
        cur = (cur == 2) ? 0 : cur + 1;

#pragma unroll
        for (int ks = 0; ks < 4; ks++) {
            uint32_t a[2][4], bfr[4][2];
#pragma unroll
            for (int mi = 0; mi < 2; mi++) {
                int r = wm + mi * 16 + rA;
                uint32_t addr = Qs + r * 128 + (((2 * ks + kbitA) ^ (r & 7)) << 4);
                LDSM4(a[mi][0], a[mi][1], a[mi][2], a[mi][3], addr);
            }
#pragma unroll
            for (int j = 0; j < 2; j++) {
                int r = wn + j * 16 + rB;
                uint32_t addr = Ks + r * 128 + (((2 * ks + kbitB) ^ (r & 7)) << 4);
                LDSM4(bfr[2 * j][0], bfr[2 * j][1], bfr[2 * j + 1][0], bfr[2 * j + 1][1], addr);
            }
#pragma unroll
            for (int mi = 0; mi < 2; mi++)
#pragma unroll
                for (int ni = 0; ni < 4; ni++)
                    mma_f16(acc[mi][ni], a[mi], bfr[ni]);
        }
    }

    const float scale = 0.03608439182435161f;   // 768^-0.5
    float* __restrict__ Sp = g_S + (size_t)b * TLEN * TLEN;
#pragma unroll
    for (int mi = 0; mi < 2; mi++)
#pragma unroll
        for (int half = 0; half < 2; half++) {
            int r = bi * 64 + wm + mi * 16 + lr + half * 8;
#pragma unroll
            for (int ni = 0; ni < 4; ni++) {
                int c = bj * 64 + wn + ni * 8 + 2 * lc;
                *(float2*)(Sp + (size_t)r * TLEN + c) =
                    make_float2(acc[mi][ni][half * 2] * scale, acc[mi][ni][half * 2 + 1] * scale);
            }
        }
}

// ---------------------------------------------------------------------------
// Softmax: one warp per row; thread handles 8 contiguous j; writes fp16 P.
// ---------------------------------------------------------------------------
__global__ void __launch_bounds__(256) softmax_kernel() {
    const int gwarp = (blockIdx.x * blockDim.x + threadIdx.x) >> 5;
    const int lane = threadIdx.x & 31;
    const int b = gwarp >> 8;
    const int i = gwarp & 255;

    const float* __restrict__ row = g_S + (size_t)b * TLEN * TLEN + (size_t)i * TLEN;
    __half* __restrict__ prow = g_ph + (size_t)b * TLEN * TLEN + (size_t)i * TLEN;

    const int j0 = lane * 8;
    float4 va = *(const float4*)(row + j0);
    float4 vb = *(const float4*)(row + j0 + 4);
    float v[8] = {va.x, va.y, va.z, va.w, vb.x, vb.y, vb.z, vb.w};

    float m = -CUDART_INF_F;
#pragma unroll
    for (int r = 0; r < 8; r++) {
        if (j0 + r > i) v[r] = -CUDART_INF_F;
        m = fmaxf(m, v[r]);
    }
#pragma unroll
    for (int off = 16; off > 0; off >>= 1)
        m = fmaxf(m, __shfl_xor_sync(0xFFFFFFFFu, m, off));

    float sum = 0.0f;
#pragma unroll
    for (int r = 0; r < 8; r++) {
        float p = expf(v[r] - m);
        v[r] = p;
        sum += p;
    }
#pragma unroll
    for (int off = 16; off > 0; off >>= 1)
        sum += __shfl_xor_sync(0xFFFFFFFFu, sum, off);

    const float inv = 1.0f / sum;
    __half2 h[4];
#pragma unroll
    for (int r = 0; r < 4; r++)
        h[r] = __floats2half2_rn(v[2 * r] * inv, v[2 * r + 1] * inv);
    *(uint4*)(prow + j0) = *(uint4*)h;
}

// ---------------------------------------------------------------------------
// PV (fp16 m16n8k16; P via ldmatrix, V via ldmatrix.trans; causal trunc).
// CTA 64x64, 128 threads, warp tile 32x32. grid = (12, 4, 128).
// V tile stored [j rows][n cols] (128B rows); trans gives col-major b-frags.
// ---------------------------------------------------------------------------
#define PTILEB (64 * 128)              // 8192 B
#define PSTGB  (2 * PTILEB)            // 16384 B per stage

__device__ __forceinline__ void pv_load_stage(uint32_t dst, const __half* __restrict__ gp,
                                              const __half* __restrict__ gv, int tid) {
#pragma unroll
    for (int i = 0; i < 4; i++) {
        int cid = tid + i * 128;
        int r = cid >> 3, c = cid & 7;
        uint32_t soff = (uint32_t)(r * 128 + ((c ^ (r & 7)) << 4));
        CP16(dst + soff, gp + (size_t)r * TLEN + c * 8);
        CP16(dst + PTILEB + soff, gv + (size_t)r * CDIM + c * 8);
    }
    CP_COMMIT();
}

__global__ void __launch_bounds__(128) pv_mma_kernel(float* __restrict__ out) {
    __shared__ char smc[2 * PSTGB];    // 32768 B
    const int bn = blockIdx.x;
    const int bm = blockIdx.y;
    const int b = blockIdx.z;

    const __half* __restrict__ gp = g_ph + ((size_t)b * TLEN + bm * 64) * TLEN;
    const __half* __restrict__ gv = g_vo + (size_t)b * TLEN * CDIM + bn * 64;
    const uint32_t sbase = smem_u32(smc);

    const int tid = threadIdx.x;
    const int wid = tid >> 5, lane = tid & 31;
    const int wm = (wid & 1) * 32;
    const int wn = (wid >> 1) * 32;
    const int lr = lane >> 2, lc = lane & 3;
    const int l7 = lane & 7;
    const int rA = ((lane >> 3) & 1) * 8 + l7;
    const int kbitA = (lane >> 4) & 1;
    // trans B: lane group g = lane>>3 selects matrix: row = ks*16 + (g&1)*8 + l7,
    // chunk = wn/8 + 2*j + (g>>1)
    const int gsel = lane >> 3;
    const int rBt = (gsel & 1) * 8 + l7;
    const int cBt = gsel >> 1;

    float acc[2][4][4] = {};
    const int nchunk = bm + 1;         // causal: j < (bm+1)*64

    pv_load_stage(sbase, gp, gv, tid);

    for (int kt = 0; kt < nchunk; kt++) {
        if (kt + 1 < nchunk) {
            pv_load_stage(sbase + ((kt + 1) & 1) * PSTGB,
                          gp + (kt + 1) * 64, gv + (size_t)(kt + 1) * 64 * CDIM, tid);
            CP_WAIT1();
        } else {
            CP_WAIT0();
        }
        __syncthreads();

        const uint32_t Ps = sbase + (kt & 1) * PSTGB;
        const uint32_t Vs = Ps + PTILEB;

#pragma unroll
        for (int ks = 0; ks < 4; ks++) {
            uint32_t a[2][4], bfr[4][2];
#pragma unroll
            for (int mi = 0; mi < 2; mi++) {
                int r = wm + mi * 16 + rA;
                uint32_t addr = Ps + r * 128 + (((2 * ks + kbitA) ^ (r & 7)) << 4);
                LDSM4(a[mi][0], a[mi][1], a[mi][2], a[mi][3], addr);
            }
#pragma unroll
            for (int j = 0; j < 2; j++) {
                int r = ks * 16 + rBt;
                int ch = (wn >> 3) + 2 * j + cBt;
                uint32_t addr = Vs + r * 128 + ((ch ^ (r & 7)) << 4);
                LDSM4T(bfr[2 * j][0], bfr[2 * j][1], bfr[2 * j + 1][0], bfr[2 * j + 1][1], addr);
            }
#pragma unroll
            for (int mi = 0; mi < 2; mi++)
#pragma unroll
                for (int ni = 0; ni < 4; ni++)
                    mma_f16(acc[mi][ni], a[mi], bfr[ni]);
        }
        __syncthreads();
    }

    float* __restrict__ op = out + (size_t)b * TLEN * CDIM;
#pragma unroll
    for (int mi = 0; mi < 2; mi++)
#pragma unroll
        for (int half = 0; half < 2; half++) {
            int r = bm * 64 + wm + mi * 16 + lr + half * 8;
#pragma unroll
            for (int ni = 0; ni < 4; ni++) {
                int c = bn * 64 + wn + ni * 8 + 2 * lc;
                *(float2*)(op + (size_t)r * CDIM + c) =
                    make_float2(acc[mi][ni][half * 2], acc[mi][ni][half * 2 + 1]);
            }
        }
}

// ---------------------------------------------------------------------------
extern "C" void kernel_launch(void* const* d_in, const int* in_sizes, int n_in,
                              void* d_out, int out_size) {
    const float* x  = (const float*)d_in[0];
    const float* Wq = (const float*)d_in[1];
    const float* Wk = (const float*)d_in[2];
    const float* Wv = (const float*)d_in[3];
    float* out = (float*)d_out;

    cudaFuncSetAttribute(qkv_mma_kernel, cudaFuncAttributeMaxDynamicSharedMemorySize, QSMEM);

    rope_table_kernel<<<(TLEN * HALF + 255) / 256, 256>>>();
    convert_x_fp16_kernel<<<(int)((size_t)MROWS * CDIM / 8 / 256), 256>>>(x);
    convert_w_fp16_kernel<<<dim3(CDIM / 32, CDIM / 32, 3), dim3(32, 8)>>>(Wq, Wk, Wv);
    qkv_mma_kernel<<<dim3(CDIM / 128, 3, MROWS / 128), 256, QSMEM>>>(x);
    scores_mma_kernel<<<dim3(TLEN / 64, TLEN / 64, BATCH), 128>>>();
    softmax_kernel<<<(MROWS * 32) / 256, 256>>>();
    pv_mma_kernel<<<dim3(CDIM / 64, TLEN / 64, BATCH), 128>>>(out);
}